// round 16
// baseline (speedup 1.0000x reference)
#include <cuda_runtime.h>
#include <cstddef>

constexpr int B_  = 2;
constexpr int S_  = 2048;
constexpr int H_  = 2304;
constexpr int NH_ = 8;
constexpr int NKV_= 4;
constexpr int HD_ = 256;
constexpr int FF_ = 9216;
constexpr int T_  = B_ * S_;     // 4096
constexpr int QD_ = NH_ * HD_;   // 2048
constexpr int KD_ = NKV_ * HD_;  // 1024
constexpr float SCALE_   = 0.0625f;
constexpr float SOFTCAP_ = 50.0f;
constexpr float EPS_     = 1e-6f;

// ------------------------------- scratch ----------------------------------
__device__ float g_h  [(size_t)T_ * H_];
__device__ float g_q  [(size_t)T_ * QD_];
__device__ float g_k  [(size_t)T_ * KD_];
__device__ float g_v  [(size_t)T_ * KD_];
__device__ float g_o  [(size_t)T_ * QD_];
__device__ float g_ao [(size_t)T_ * H_];
__device__ float g_h2 [(size_t)T_ * H_];
__device__ float g_f  [(size_t)T_ * H_];
__device__ float g_gate[(size_t)T_ * FF_];
__device__ float g_up  [(size_t)T_ * FF_];
__device__ float g_mlp [(size_t)T_ * H_];

#define DEV_INLINE __device__ __forceinline__

DEV_INLINE unsigned long long pack_dup(float a) {
    unsigned long long r;
    asm("mov.b64 %0, {%1, %1};" : "=l"(r) : "f"(a));
    return r;
}
DEV_INLINE void fma2(unsigned long long& d, unsigned long long a, unsigned long long b) {
    asm("fma.rn.f32x2 %0, %1, %2, %0;" : "+l"(d) : "l"(a), "l"(b));
}
DEV_INLINE float2 unpk(unsigned long long v) {
    float2 f;
    asm("mov.b64 {%0, %1}, %2;" : "=f"(f.x), "=f"(f.y) : "l"(v));
    return f;
}

// ------------------------------ rmsnorm -----------------------------------
// out[row] = (res ? res[row] : 0) + normalize(in[row]) * (1+g).  H = 9*256.
__global__ void rmsnorm_kernel(const float* __restrict__ in, const float* __restrict__ g,
                               const float* __restrict__ res, float* __restrict__ out)
{
    const int row = blockIdx.x, tid = threadIdx.x;
    const float* xr = in + (size_t)row * H_;
    float v[9];
    float ss = 0.f;
#pragma unroll
    for (int i = 0; i < 9; i++) { v[i] = xr[tid + i * 256]; ss += v[i] * v[i]; }
#pragma unroll
    for (int off = 16; off > 0; off >>= 1)
        ss += __shfl_xor_sync(0xffffffffu, ss, off);
    __shared__ float red[8];
    if ((tid & 31) == 0) red[tid >> 5] = ss;
    __syncthreads();
    float tot = red[0];
#pragma unroll
    for (int i = 1; i < 8; i++) tot += red[i];
    const float r = rsqrtf(tot * (1.0f / (float)H_) + EPS_);
    float* orow = out + (size_t)row * H_;
    const float* rrow = res ? res + (size_t)row * H_ : nullptr;
#pragma unroll
    for (int i = 0; i < 9; i++) {
        const int c = tid + i * 256;
        float val = v[i] * r * (1.f + g[c]);
        if (rrow) val += rrow[c];
        orow[c] = val;
    }
}

// ------------------------------- SGEMM ------------------------------------
// C[M,N] = A[M,K] @ B[K,N]; 128x128x8 tile, 256 thr, 8x8 micro, FFMA2.
__global__ void __launch_bounds__(256, 2)
sgemm_kernel(const float* __restrict__ A, const float* __restrict__ Bm,
             float* __restrict__ C, int M, int N, int K)
{
    constexpr int BM = 128, BN = 128, BK = 8;
    __shared__ __align__(16) float As[2][BK][BM + 4];
    __shared__ __align__(16) float Bs[2][BK][BN + 4];
    const int tid = threadIdx.x;
    const int bx = blockIdx.x, by = blockIdx.y;

    const int arow = tid >> 1, acol = (tid & 1) << 2;
    const int brow = tid >> 5, bcol = (tid & 31) << 2;
    const float* Ap = A + (size_t)(by * BM + arow) * K + acol;
    const float* Bp = Bm + (size_t)brow * N + (size_t)bx * BN + bcol;

    const int tr = tid >> 4, tc = tid & 15;

    unsigned long long acc[8][4];
#pragma unroll
    for (int i = 0; i < 8; i++)
#pragma unroll
        for (int j = 0; j < 4; j++) acc[i][j] = 0ull;

    float4 a4 = *(const float4*)Ap;
    float4 b4 = *(const float4*)Bp;
    As[0][acol + 0][arow] = a4.x;
    As[0][acol + 1][arow] = a4.y;
    As[0][acol + 2][arow] = a4.z;
    As[0][acol + 3][arow] = a4.w;
    *(float4*)&Bs[0][brow][bcol] = b4;
    __syncthreads();

    const int ntiles = K / BK;
    for (int t = 0; t < ntiles; t++) {
        const int cur = t & 1;
        if (t + 1 < ntiles) {
            a4 = *(const float4*)(Ap + (size_t)(t + 1) * BK);
            b4 = *(const float4*)(Bp + (size_t)(t + 1) * BK * N);
        }
#pragma unroll
        for (int kk = 0; kk < BK; kk++) {
            const float4 af0 = *(const float4*)&As[cur][kk][tr * 8];
            const float4 af1 = *(const float4*)&As[cur][kk][tr * 8 + 4];
            const ulonglong2 bf0 = *(const ulonglong2*)&Bs[cur][kk][tc * 8];
            const ulonglong2 bf1 = *(const ulonglong2*)&Bs[cur][kk][tc * 8 + 4];
            const float av[8] = {af0.x, af0.y, af0.z, af0.w, af1.x, af1.y, af1.z, af1.w};
#pragma unroll
            for (int i = 0; i < 8; i++) {
                const unsigned long long ad = pack_dup(av[i]);
                fma2(acc[i][0], ad, bf0.x);
                fma2(acc[i][1], ad, bf0.y);
                fma2(acc[i][2], ad, bf1.x);
                fma2(acc[i][3], ad, bf1.y);
            }
        }
        if (t + 1 < ntiles) {
            const int nxt = cur ^ 1;
            As[nxt][acol + 0][arow] = a4.x;
            As[nxt][acol + 1][arow] = a4.y;
            As[nxt][acol + 2][arow] = a4.z;
            As[nxt][acol + 3][arow] = a4.w;
            *(float4*)&Bs[nxt][brow][bcol] = b4;
        }
        __syncthreads();
    }

#pragma unroll
    for (int i = 0; i < 8; i++) {
        const float2 p0 = unpk(acc[i][0]), p1 = unpk(acc[i][1]);
        const float2 p2 = unpk(acc[i][2]), p3 = unpk(acc[i][3]);
        float* cp = C + (size_t)(by * BM + tr * 8 + i) * N + (size_t)bx * BN + tc * 8;
        *(float4*)cp       = make_float4(p0.x, p0.y, p1.x, p1.y);
        *(float4*)(cp + 4) = make_float4(p2.x, p2.y, p3.x, p3.y);
    }
}

// -------------------------------- RoPE ------------------------------------
template <int NHEADS>
__global__ void rope_kernel(float* __restrict__ p)
{
    const int idx = blockIdx.x * blockDim.x + threadIdx.x; // T*NHEADS*128
    const int d  = idx & 127;
    const int th = idx >> 7;
    const int h  = th & (NHEADS - 1);
    const int t  = th / NHEADS;
    const int pos = t & (S_ - 1);
    const float invf = expf((float)d * (-9.210340371976184f / 128.0f)); // 10000^(-d/128)
    const float ang  = (float)pos * invf;
    float sn, cs;
    sincosf(ang, &sn, &cs);
    float* base = p + (size_t)t * (NHEADS * HD_) + h * HD_ + d;
    const float x0 = base[0], x1 = base[128];
    base[0]   = x0 * cs - x1 * sn;
    base[128] = x1 * cs + x0 * sn;
}

// ---------------------------- flash attention ------------------------------
constexpr int ATTN_SMEM_BYTES = (256 * 68 * 2 + 64 * 256 + 64 * 68 + 3 * 64) * 4;

__global__ void __launch_bounds__(256, 1)
attn_kernel(const float* __restrict__ Q, const float* __restrict__ Kg,
            const float* __restrict__ Vg, float* __restrict__ O)
{
    extern __shared__ __align__(16) float sm[];
    float* Qt  = sm;              // [256][68]  (d-major, i minor)
    float* Kt  = Qt + 256 * 68;   // [256][68]
    float* Vs  = Kt + 256 * 68;   // [64][256]
    float* Ps  = Vs + 64 * 256;   // [64][68]
    float* m_s = Ps + 64 * 68;
    float* l_s = m_s + 64;
    float* c_s = l_s + 64;

    const int tid = threadIdx.x;
    const int qb = blockIdx.x, h = blockIdx.y, b = blockIdx.z;
    const int q0 = qb * 64;
    const int ty = tid >> 4, tx = tid & 15;
    const int g  = h >> 1;        // GQA repeat=2

    const float* qbase = Q + (size_t)(b * S_ + q0) * QD_ + h * HD_;
#pragma unroll
    for (int l = 0; l < 16; l++) {
        const int lin = tid + l * 256;
        const int row = lin >> 6;
        const int d0  = (lin & 63) << 2;
        const float4 qa = *(const float4*)(qbase + (size_t)row * QD_ + d0);
        Qt[(d0 + 0) * 68 + row] = qa.x;
        Qt[(d0 + 1) * 68 + row] = qa.y;
        Qt[(d0 + 2) * 68 + row] = qa.z;
        Qt[(d0 + 3) * 68 + row] = qa.w;
    }
    if (tid < 64) { m_s[tid] = -1e30f; l_s[tid] = 0.f; }

    float oacc[4][16];
#pragma unroll
    for (int r = 0; r < 4; r++)
#pragma unroll
        for (int u = 0; u < 16; u++) oacc[r][u] = 0.f;

    const float* kbase = Kg + (size_t)(b * S_) * KD_ + g * HD_;
    const float* vbase = Vg + (size_t)(b * S_) * KD_ + g * HD_;

    for (int t = 0; t <= qb; t++) {
        const int j0 = t * 64;
        __syncthreads();
#pragma unroll
        for (int l = 0; l < 16; l++) {
            const int lin = tid + l * 256;
            const int row = lin >> 6;
            const int d0  = (lin & 63) << 2;
            const float4 kv = *(const float4*)(kbase + (size_t)(j0 + row) * KD_ + d0);
            Kt[(d0 + 0) * 68 + row] = kv.x;
            Kt[(d0 + 1) * 68 + row] = kv.y;
            Kt[(d0 + 2) * 68 + row] = kv.z;
            Kt[(d0 + 3) * 68 + row] = kv.w;
            *(float4*)&Vs[row * 256 + d0] =
                *(const float4*)(vbase + (size_t)(j0 + row) * KD_ + d0);
        }
        __syncthreads();

        float s[4][4];
#pragma unroll
        for (int r = 0; r < 4; r++)
#pragma unroll
            for (int c = 0; c < 4; c++) s[r][c] = 0.f;
#pragma unroll 8
        for (int d = 0; d < 256; d++) {
            const float4 qa = *(const float4*)&Qt[d * 68 + ty * 4];
            const float4 ka = *(const float4*)&Kt[d * 68 + tx * 4];
            s[0][0] += qa.x * ka.x; s[0][1] += qa.x * ka.y; s[0][2] += qa.x * ka.z; s[0][3] += qa.x * ka.w;
            s[1][0] += qa.y * ka.x; s[1][1] += qa.y * ka.y; s[1][2] += qa.y * ka.z; s[1][3] += qa.y * ka.w;
            s[2][0] += qa.z * ka.x; s[2][1] += qa.z * ka.y; s[2][2] += qa.z * ka.z; s[2][3] += qa.z * ka.w;
            s[3][0] += qa.w * ka.x; s[3][1] += qa.w * ka.y; s[3][2] += qa.w * ka.z; s[3][3] += qa.w * ka.w;
        }

        float mx[4];
#pragma unroll
        for (int r = 0; r < 4; r++) {
            mx[r] = -1e30f;
#pragma unroll
            for (int c = 0; c < 4; c++) {
                float sv = SOFTCAP_ * tanhf(s[r][c] * (SCALE_ / SOFTCAP_));
                const bool masked = (j0 + tx * 4 + c) > (q0 + ty * 4 + r);
                sv = masked ? -1e9f : sv;
                s[r][c] = sv;
                mx[r] = fmaxf(mx[r], sv);
            }
        }
#pragma unroll
        for (int r = 0; r < 4; r++)
#pragma unroll
            for (int off = 8; off > 0; off >>= 1)
                mx[r] = fmaxf(mx[r], __shfl_xor_sync(0xffffffffu, mx[r], off));
        if (tx == 0) {
#pragma unroll
            for (int r = 0; r < 4; r++) {
                const int i = ty * 4 + r;
                const float mo = m_s[i];
                const float mn = fmaxf(mo, mx[r]);
                c_s[i] = __expf(mo - mn);
                m_s[i] = mn;
            }
        }
        __syncthreads();

        float rs[4];
#pragma unroll
        for (int r = 0; r < 4; r++) {
            const float mn = m_s[ty * 4 + r];
            rs[r] = 0.f;
#pragma unroll
            for (int c = 0; c < 4; c++) {
                const float pv = __expf(s[r][c] - mn);
                s[r][c] = pv;
                rs[r] += pv;
            }
        }
#pragma unroll
        for (int r = 0; r < 4; r++)
#pragma unroll
            for (int off = 8; off > 0; off >>= 1)
                rs[r] += __shfl_xor_sync(0xffffffffu, rs[r], off);
        if (tx == 0) {
#pragma unroll
            for (int r = 0; r < 4; r++) {
                const int i = ty * 4 + r;
                l_s[i] = l_s[i] * c_s[i] + rs[r];
            }
        }
#pragma unroll
        for (int r = 0; r < 4; r++)
            *(float4*)&Ps[(ty * 4 + r) * 68 + tx * 4] =
                make_float4(s[r][0], s[r][1], s[r][2], s[r][3]);
        __syncthreads();

#pragma unroll
        for (int r = 0; r < 4; r++) {
            const float cv = c_s[ty * 4 + r];
#pragma unroll
            for (int u = 0; u < 16; u++) oacc[r][u] *= cv;
        }
#pragma unroll 2
        for (int j = 0; j < 64; j++) {
            const float p0 = Ps[(ty * 4 + 0) * 68 + j];
            const float p1 = Ps[(ty * 4 + 1) * 68 + j];
            const float p2 = Ps[(ty * 4 + 2) * 68 + j];
            const float p3 = Ps[(ty * 4 + 3) * 68 + j];
            const float* vrow = &Vs[j * 256 + tx * 4];
#pragma unroll
            for (int c = 0; c < 4; c++) {
                const float4 vv = *(const float4*)(vrow + c * 64);
                oacc[0][c * 4 + 0] += p0 * vv.x; oacc[0][c * 4 + 1] += p0 * vv.y;
                oacc[0][c * 4 + 2] += p0 * vv.z; oacc[0][c * 4 + 3] += p0 * vv.w;
                oacc[1][c * 4 + 0] += p1 * vv.x; oacc[1][c * 4 + 1] += p1 * vv.y;
                oacc[1][c * 4 + 2] += p1 * vv.z; oacc[1][c * 4 + 3] += p1 * vv.w;
                oacc[2][c * 4 + 0] += p2 * vv.x; oacc[2][c * 4 + 1] += p2 * vv.y;
                oacc[2][c * 4 + 2] += p2 * vv.z; oacc[2][c * 4 + 3] += p2 * vv.w;
                oacc[3][c * 4 + 0] += p3 * vv.x; oacc[3][c * 4 + 1] += p3 * vv.y;
                oacc[3][c * 4 + 2] += p3 * vv.z; oacc[3][c * 4 + 3] += p3 * vv.w;
            }
        }
    }

    float* obase = O + (size_t)(b * S_ + q0) * QD_ + h * HD_;
#pragma unroll
    for (int r = 0; r < 4; r++) {
        const float inv = 1.f / l_s[ty * 4 + r];
        float* orow = obase + (size_t)(ty * 4 + r) * QD_ + tx * 4;
#pragma unroll
        for (int c = 0; c < 4; c++) {
            *(float4*)(orow + c * 64) = make_float4(
                oacc[r][c * 4 + 0] * inv, oacc[r][c * 4 + 1] * inv,
                oacc[r][c * 4 + 2] * inv, oacc[r][c * 4 + 3] * inv);
        }
    }
}

// -------------------------------- GeGLU -----------------------------------
DEV_INLINE float gelu_tanh(float x) {
    const float x3 = x * x * x;
    return 0.5f * x * (1.f + tanhf(0.7978845608028654f * (x + 0.044715f * x3)));
}
__global__ void geglu_kernel(float* __restrict__ gate, const float* __restrict__ up)
{
    const size_t i = (size_t)blockIdx.x * blockDim.x + threadIdx.x;
    float4 gv = ((const float4*)gate)[i];
    const float4 uv = ((const float4*)up)[i];
    gv.x = gelu_tanh(gv.x) * uv.x;
    gv.y = gelu_tanh(gv.y) * uv.y;
    gv.z = gelu_tanh(gv.z) * uv.z;
    gv.w = gelu_tanh(gv.w) * uv.w;
    ((float4*)gate)[i] = gv;
}

// ------------------------------- launch ------------------------------------
extern "C" void kernel_launch(void* const* d_in, const int* in_sizes, int n_in,
                              void* d_out, int out_size)
{
    (void)in_sizes; (void)n_in; (void)out_size;
    const float* x         = (const float*)d_in[0];
    // d_in[1] = causal mask, handled analytically in attn_kernel
    const float* wq        = (const float*)d_in[2];
    const float* wk        = (const float*)d_in[3];
    const float* wv        = (const float*)d_in[4];
    const float* wo        = (const float*)d_in[5];
    const float* w_gate    = (const float*)d_in[6];
    const float* w_up      = (const float*)d_in[7];
    const float* w_down    = (const float*)d_in[8];
    const float* g_in_p    = (const float*)d_in[9];
    const float* g_post_at = (const float*)d_in[10];
    const float* g_preff   = (const float*)d_in[11];
    const float* g_postff  = (const float*)d_in[12];
    float* out = (float*)d_out;

    static bool attr_set = false;
    if (!attr_set) {
        cudaFuncSetAttribute(attn_kernel, cudaFuncAttributeMaxDynamicSharedMemorySize,
                             ATTN_SMEM_BYTES);
        attr_set = true;
    }

    // 1) h = rmsnorm(x, g_in)
    rmsnorm_kernel<<<T_, 256>>>(x, g_in_p, nullptr, g_h);
    // 2) QKV projections
    sgemm_kernel<<<dim3(QD_ / 128, T_ / 128), 256>>>(g_h, wq, g_q, T_, QD_, H_);
    sgemm_kernel<<<dim3(KD_ / 128, T_ / 128), 256>>>(g_h, wk, g_k, T_, KD_, H_);
    sgemm_kernel<<<dim3(KD_ / 128, T_ / 128), 256>>>(g_h, wv, g_v, T_, KD_, H_);
    // 3) RoPE
    rope_kernel<NH_ ><<<T_ * NH_  * 128 / 256, 256>>>(g_q);
    rope_kernel<NKV_><<<T_ * NKV_ * 128 / 256, 256>>>(g_k);
    // 4) flash attention (causal, softcap, GQA)
    attn_kernel<<<dim3(S_ / 64, NH_, B_), 256, ATTN_SMEM_BYTES>>>(g_q, g_k, g_v, g_o);
    // 5) O projection
    sgemm_kernel<<<dim3(H_ / 128, T_ / 128), 256>>>(g_o, wo, g_ao, T_, H_, QD_);
    // 6) h2 = x + rmsnorm(attn_out, g_post_attn)
    rmsnorm_kernel<<<T_, 256>>>(g_ao, g_post_at, x, g_h2);
    // 7) f = rmsnorm(h2, g_pre_ff)
    rmsnorm_kernel<<<T_, 256>>>(g_h2, g_preff, nullptr, g_f);
    // 8) gate/up projections
    sgemm_kernel<<<dim3(FF_ / 128, T_ / 128), 256>>>(g_f, w_gate, g_gate, T_, FF_, H_);
    sgemm_kernel<<<dim3(FF_ / 128, T_ / 128), 256>>>(g_f, w_up,   g_up,   T_, FF_, H_);
    // 9) GeGLU (in-place into gate)
    geglu_kernel<<<(size_t)T_ * FF_ / 4 / 256, 256>>>(g_gate, g_up);
    // 10) down projection
    sgemm_kernel<<<dim3(H_ / 128, T_ / 128), 256>>>(g_gate, w_down, g_mlp, T_, H_, FF_);
    // 11) out = h2 + rmsnorm(mlp, g_post_ff)
    rmsnorm_kernel<<<T_, 256>>>(g_mlp, g_postff, g_h2, out);
}

// round 17
// speedup vs baseline: 1.0381x; 1.0381x over previous
#include <cuda_runtime.h>
#include <cstddef>

constexpr int B_  = 2;
constexpr int S_  = 2048;
constexpr int H_  = 2304;
constexpr int NH_ = 8;
constexpr int NKV_= 4;
constexpr int HD_ = 256;
constexpr int FF_ = 9216;
constexpr int T_  = B_ * S_;     // 4096
constexpr int QD_ = NH_ * HD_;   // 2048
constexpr int KD_ = NKV_ * HD_;  // 1024
constexpr float SCALE_   = 0.0625f;
constexpr float SOFTCAP_ = 50.0f;
constexpr float EPS_     = 1e-6f;

// ------------------------------- scratch ----------------------------------
__device__ float g_h  [(size_t)T_ * H_];
__device__ float g_q  [(size_t)T_ * QD_];
__device__ float g_k  [(size_t)T_ * KD_];
__device__ float g_v  [(size_t)T_ * KD_];
__device__ float g_o  [(size_t)T_ * QD_];
__device__ float g_ao [(size_t)T_ * H_];
__device__ float g_h2 [(size_t)T_ * H_];
__device__ float g_f  [(size_t)T_ * H_];
__device__ float g_gate[(size_t)T_ * FF_];
__device__ float g_up  [(size_t)T_ * FF_];
__device__ float g_mlp [(size_t)T_ * H_];

#define DEV_INLINE __device__ __forceinline__

DEV_INLINE unsigned long long pack_dup(float a) {
    unsigned long long r;
    asm("mov.b64 %0, {%1, %1};" : "=l"(r) : "f"(a));
    return r;
}
DEV_INLINE void fma2(unsigned long long& d, unsigned long long a, unsigned long long b) {
    asm("fma.rn.f32x2 %0, %1, %2, %0;" : "+l"(d) : "l"(a), "l"(b));
}
DEV_INLINE float2 unpk(unsigned long long v) {
    float2 f;
    asm("mov.b64 {%0, %1}, %2;" : "=f"(f.x), "=f"(f.y) : "l"(v));
    return f;
}

// ------------------------------ rmsnorm -----------------------------------
// out[row] = (res ? res[row] : 0) + normalize(in[row]) * (1+g).  H = 9*256.
__global__ void rmsnorm_kernel(const float* __restrict__ in, const float* __restrict__ g,
                               const float* __restrict__ res, float* __restrict__ out)
{
    const int row = blockIdx.x, tid = threadIdx.x;
    const float* xr = in + (size_t)row * H_;
    float v[9];
    float ss = 0.f;
#pragma unroll
    for (int i = 0; i < 9; i++) { v[i] = xr[tid + i * 256]; ss += v[i] * v[i]; }
#pragma unroll
    for (int off = 16; off > 0; off >>= 1)
        ss += __shfl_xor_sync(0xffffffffu, ss, off);
    __shared__ float red[8];
    if ((tid & 31) == 0) red[tid >> 5] = ss;
    __syncthreads();
    float tot = red[0];
#pragma unroll
    for (int i = 1; i < 8; i++) tot += red[i];
    const float r = rsqrtf(tot * (1.0f / (float)H_) + EPS_);
    float* orow = out + (size_t)row * H_;
    const float* rrow = res ? res + (size_t)row * H_ : nullptr;
#pragma unroll
    for (int i = 0; i < 9; i++) {
        const int c = tid + i * 256;
        float val = v[i] * r * (1.f + g[c]);
        if (rrow) val += rrow[c];
        orow[c] = val;
    }
}

// ------------------------------- SGEMM ------------------------------------
// C[M,N] = A[M,K] @ B[K,N]; 128x128x8 tile, 256 thr, 8x8 micro, FFMA2.
__global__ void __launch_bounds__(256, 2)
sgemm_kernel(const float* __restrict__ A, const float* __restrict__ Bm,
             float* __restrict__ C, int M, int N, int K)
{
    constexpr int BM = 128, BN = 128, BK = 8;
    __shared__ __align__(16) float As[2][BK][BM + 4];
    __shared__ __align__(16) float Bs[2][BK][BN + 4];
    const int tid = threadIdx.x;
    const int bx = blockIdx.x, by = blockIdx.y;

    const int arow = tid >> 1, acol = (tid & 1) << 2;
    const int brow = tid >> 5, bcol = (tid & 31) << 2;
    const float* Ap = A + (size_t)(by * BM + arow) * K + acol;
    const float* Bp = Bm + (size_t)brow * N + (size_t)bx * BN + bcol;

    const int tr = tid >> 4, tc = tid & 15;

    unsigned long long acc[8][4];
#pragma unroll
    for (int i = 0; i < 8; i++)
#pragma unroll
        for (int j = 0; j < 4; j++) acc[i][j] = 0ull;

    float4 a4 = *(const float4*)Ap;
    float4 b4 = *(const float4*)Bp;
    As[0][acol + 0][arow] = a4.x;
    As[0][acol + 1][arow] = a4.y;
    As[0][acol + 2][arow] = a4.z;
    As[0][acol + 3][arow] = a4.w;
    *(float4*)&Bs[0][brow][bcol] = b4;
    __syncthreads();

    const int ntiles = K / BK;
    for (int t = 0; t < ntiles; t++) {
        const int cur = t & 1;
        if (t + 1 < ntiles) {
            a4 = *(const float4*)(Ap + (size_t)(t + 1) * BK);
            b4 = *(const float4*)(Bp + (size_t)(t + 1) * BK * N);
        }
#pragma unroll
        for (int kk = 0; kk < BK; kk++) {
            const float4 af0 = *(const float4*)&As[cur][kk][tr * 8];
            const float4 af1 = *(const float4*)&As[cur][kk][tr * 8 + 4];
            const ulonglong2 bf0 = *(const ulonglong2*)&Bs[cur][kk][tc * 8];
            const ulonglong2 bf1 = *(const ulonglong2*)&Bs[cur][kk][tc * 8 + 4];
            const float av[8] = {af0.x, af0.y, af0.z, af0.w, af1.x, af1.y, af1.z, af1.w};
#pragma unroll
            for (int i = 0; i < 8; i++) {
                const unsigned long long ad = pack_dup(av[i]);
                fma2(acc[i][0], ad, bf0.x);
                fma2(acc[i][1], ad, bf0.y);
                fma2(acc[i][2], ad, bf1.x);
                fma2(acc[i][3], ad, bf1.y);
            }
        }
        if (t + 1 < ntiles) {
            const int nxt = cur ^ 1;
            As[nxt][acol + 0][arow] = a4.x;
            As[nxt][acol + 1][arow] = a4.y;
            As[nxt][acol + 2][arow] = a4.z;
            As[nxt][acol + 3][arow] = a4.w;
            *(float4*)&Bs[nxt][brow][bcol] = b4;
        }
        __syncthreads();
    }

#pragma unroll
    for (int i = 0; i < 8; i++) {
        const float2 p0 = unpk(acc[i][0]), p1 = unpk(acc[i][1]);
        const float2 p2 = unpk(acc[i][2]), p3 = unpk(acc[i][3]);
        float* cp = C + (size_t)(by * BM + tr * 8 + i) * N + (size_t)bx * BN + tc * 8;
        *(float4*)cp       = make_float4(p0.x, p0.y, p1.x, p1.y);
        *(float4*)(cp + 4) = make_float4(p2.x, p2.y, p3.x, p3.y);
    }
}

// -------------------------------- RoPE ------------------------------------
template <int NHEADS>
__global__ void rope_kernel(float* __restrict__ p)
{
    const int idx = blockIdx.x * blockDim.x + threadIdx.x; // T*NHEADS*128
    const int d  = idx & 127;
    const int th = idx >> 7;
    const int h  = th & (NHEADS - 1);
    const int t  = th / NHEADS;
    const int pos = t & (S_ - 1);
    const float invf = expf((float)d * (-9.210340371976184f / 128.0f)); // 10000^(-d/128)
    const float ang  = (float)pos * invf;
    float sn, cs;
    sincosf(ang, &sn, &cs);
    float* base = p + (size_t)t * (NHEADS * HD_) + h * HD_ + d;
    const float x0 = base[0], x1 = base[128];
    base[0]   = x0 * cs - x1 * sn;
    base[128] = x1 * cs + x0 * sn;
}

// ---------------------------- flash attention ------------------------------
constexpr int ATTN_SMEM_BYTES = (256 * 68 * 2 + 64 * 256 + 64 * 68 + 3 * 64) * 4;

__global__ void __launch_bounds__(256, 1)
attn_kernel(const float* __restrict__ Q, const float* __restrict__ Kg,
            const float* __restrict__ Vg, float* __restrict__ O)
{
    extern __shared__ __align__(16) float sm[];
    float* Qt  = sm;              // [256][68]  (d-major, i minor)
    float* Kt  = Qt + 256 * 68;   // [256][68]
    float* Vs  = Kt + 256 * 68;   // [64][256]
    float* Ps  = Vs + 64 * 256;   // [64][68]
    float* m_s = Ps + 64 * 68;
    float* l_s = m_s + 64;
    float* c_s = l_s + 64;

    const int tid = threadIdx.x;
    const int qb = blockIdx.x, h = blockIdx.y, b = blockIdx.z;
    const int q0 = qb * 64;
    const int ty = tid >> 4, tx = tid & 15;
    const int g  = h >> 1;        // GQA repeat=2

    const float* qbase = Q + (size_t)(b * S_ + q0) * QD_ + h * HD_;
#pragma unroll
    for (int l = 0; l < 16; l++) {
        const int lin = tid + l * 256;
        const int row = lin >> 6;
        const int d0  = (lin & 63) << 2;
        const float4 qa = *(const float4*)(qbase + (size_t)row * QD_ + d0);
        Qt[(d0 + 0) * 68 + row] = qa.x;
        Qt[(d0 + 1) * 68 + row] = qa.y;
        Qt[(d0 + 2) * 68 + row] = qa.z;
        Qt[(d0 + 3) * 68 + row] = qa.w;
    }
    if (tid < 64) { m_s[tid] = -1e30f; l_s[tid] = 0.f; }

    float oacc[4][16];
#pragma unroll
    for (int r = 0; r < 4; r++)
#pragma unroll
        for (int u = 0; u < 16; u++) oacc[r][u] = 0.f;

    const float* kbase = Kg + (size_t)(b * S_) * KD_ + g * HD_;
    const float* vbase = Vg + (size_t)(b * S_) * KD_ + g * HD_;

    for (int t = 0; t <= qb; t++) {
        const int j0 = t * 64;
        __syncthreads();
#pragma unroll
        for (int l = 0; l < 16; l++) {
            const int lin = tid + l * 256;
            const int row = lin >> 6;
            const int d0  = (lin & 63) << 2;
            const float4 kv = *(const float4*)(kbase + (size_t)(j0 + row) * KD_ + d0);
            Kt[(d0 + 0) * 68 + row] = kv.x;
            Kt[(d0 + 1) * 68 + row] = kv.y;
            Kt[(d0 + 2) * 68 + row] = kv.z;
            Kt[(d0 + 3) * 68 + row] = kv.w;
            *(float4*)&Vs[row * 256 + d0] =
                *(const float4*)(vbase + (size_t)(j0 + row) * KD_ + d0);
        }
        __syncthreads();

        float s[4][4];
#pragma unroll
        for (int r = 0; r < 4; r++)
#pragma unroll
            for (int c = 0; c < 4; c++) s[r][c] = 0.f;
#pragma unroll 8
        for (int d = 0; d < 256; d++) {
            const float4 qa = *(const float4*)&Qt[d * 68 + ty * 4];
            const float4 ka = *(const float4*)&Kt[d * 68 + tx * 4];
            s[0][0] += qa.x * ka.x; s[0][1] += qa.x * ka.y; s[0][2] += qa.x * ka.z; s[0][3] += qa.x * ka.w;
            s[1][0] += qa.y * ka.x; s[1][1] += qa.y * ka.y; s[1][2] += qa.y * ka.z; s[1][3] += qa.y * ka.w;
            s[2][0] += qa.z * ka.x; s[2][1] += qa.z * ka.y; s[2][2] += qa.z * ka.z; s[2][3] += qa.z * ka.w;
            s[3][0] += qa.w * ka.x; s[3][1] += qa.w * ka.y; s[3][2] += qa.w * ka.z; s[3][3] += qa.w * ka.w;
        }

        float mx[4];
#pragma unroll
        for (int r = 0; r < 4; r++) {
            mx[r] = -1e30f;
#pragma unroll
            for (int c = 0; c < 4; c++) {
                float sv = SOFTCAP_ * tanhf(s[r][c] * (SCALE_ / SOFTCAP_));
                const bool masked = (j0 + tx * 4 + c) > (q0 + ty * 4 + r);
                sv = masked ? -1e9f : sv;
                s[r][c] = sv;
                mx[r] = fmaxf(mx[r], sv);
            }
        }
#pragma unroll
        for (int r = 0; r < 4; r++)
#pragma unroll
            for (int off = 8; off > 0; off >>= 1)
                mx[r] = fmaxf(mx[r], __shfl_xor_sync(0xffffffffu, mx[r], off));
        if (tx == 0) {
#pragma unroll
            for (int r = 0; r < 4; r++) {
                const int i = ty * 4 + r;
                const float mo = m_s[i];
                const float mn = fmaxf(mo, mx[r]);
                c_s[i] = __expf(mo - mn);
                m_s[i] = mn;
            }
        }
        __syncthreads();

        float rs[4];
#pragma unroll
        for (int r = 0; r < 4; r++) {
            const float mn = m_s[ty * 4 + r];
            rs[r] = 0.f;
#pragma unroll
            for (int c = 0; c < 4; c++) {
                const float pv = __expf(s[r][c] - mn);
                s[r][c] = pv;
                rs[r] += pv;
            }
        }
#pragma unroll
        for (int r = 0; r < 4; r++)
#pragma unroll
            for (int off = 8; off > 0; off >>= 1)
                rs[r] += __shfl_xor_sync(0xffffffffu, rs[r], off);
        if (tx == 0) {
#pragma unroll
            for (int r = 0; r < 4; r++) {
                const int i = ty * 4 + r;
                l_s[i] = l_s[i] * c_s[i] + rs[r];
            }
        }
#pragma unroll
        for (int r = 0; r < 4; r++)
            *(float4*)&Ps[(ty * 4 + r) * 68 + tx * 4] =
                make_float4(s[r][0], s[r][1], s[r][2], s[r][3]);
        __syncthreads();

#pragma unroll
        for (int r = 0; r < 4; r++) {
            const float cv = c_s[ty * 4 + r];
#pragma unroll
            for (int u = 0; u < 16; u++) oacc[r][u] *= cv;
        }
#pragma unroll 2
        for (int j = 0; j < 64; j++) {
            const float p0 = Ps[(ty * 4 + 0) * 68 + j];
            const float p1 = Ps[(ty * 4 + 1) * 68 + j];
            const float p2 = Ps[(ty * 4 + 2) * 68 + j];
            const float p3 = Ps[(ty * 4 + 3) * 68 + j];
            const float* vrow = &Vs[j * 256 + tx * 4];
#pragma unroll
            for (int c = 0; c < 4; c++) {
                const float4 vv = *(const float4*)(vrow + c * 64);
                oacc[0][c * 4 + 0] += p0 * vv.x; oacc[0][c * 4 + 1] += p0 * vv.y;
                oacc[0][c * 4 + 2] += p0 * vv.z; oacc[0][c * 4 + 3] += p0 * vv.w;
                oacc[1][c * 4 + 0] += p1 * vv.x; oacc[1][c * 4 + 1] += p1 * vv.y;
                oacc[1][c * 4 + 2] += p1 * vv.z; oacc[1][c * 4 + 3] += p1 * vv.w;
                oacc[2][c * 4 + 0] += p2 * vv.x; oacc[2][c * 4 + 1] += p2 * vv.y;
                oacc[2][c * 4 + 2] += p2 * vv.z; oacc[2][c * 4 + 3] += p2 * vv.w;
                oacc[3][c * 4 + 0] += p3 * vv.x; oacc[3][c * 4 + 1] += p3 * vv.y;
                oacc[3][c * 4 + 2] += p3 * vv.z; oacc[3][c * 4 + 3] += p3 * vv.w;
            }
        }
    }

    float* obase = O + (size_t)(b * S_ + q0) * QD_ + h * HD_;
#pragma unroll
    for (int r = 0; r < 4; r++) {
        const float inv = 1.f / l_s[ty * 4 + r];
        float* orow = obase + (size_t)(ty * 4 + r) * QD_ + tx * 4;
#pragma unroll
        for (int c = 0; c < 4; c++) {
            *(float4*)(orow + c * 64) = make_float4(
                oacc[r][c * 4 + 0] * inv, oacc[r][c * 4 + 1] * inv,
                oacc[r][c * 4 + 2] * inv, oacc[r][c * 4 + 3] * inv);
        }
    }
}

// -------------------------------- GeGLU -----------------------------------
DEV_INLINE float gelu_tanh(float x) {
    const float x3 = x * x * x;
    return 0.5f * x * (1.f + tanhf(0.7978845608028654f * (x + 0.044715f * x3)));
}
__global__ void geglu_kernel(float* __restrict__ gate, const float* __restrict__ up)
{
    const size_t i = (size_t)blockIdx.x * blockDim.x + threadIdx.x;
    float4 gv = ((const float4*)gate)[i];
    const float4 uv = ((const float4*)up)[i];
    gv.x = gelu_tanh(gv.x) * uv.x;
    gv.y = gelu_tanh(gv.y) * uv.y;
    gv.z = gelu_tanh(gv.z) * uv.z;
    gv.w = gelu_tanh(gv.w) * uv.w;
    ((float4*)gate)[i] = gv;
}

// ------------------------------- launch ------------------------------------
extern "C" void kernel_launch(void* const* d_in, const int* in_sizes, int n_in,
                              void* d_out, int out_size)
{
    (void)in_sizes; (void)n_in; (void)out_size;
    const float* x         = (const float*)d_in[0];
    // d_in[1] = causal mask, handled analytically in attn_kernel
    const float* wq        = (const float*)d_in[2];
    const float* wk        = (const float*)d_in[3];
    const float* wv        = (const float*)d_in[4];
    const float* wo        = (const float*)d_in[5];
    const float* w_gate    = (const float*)d_in[6];
    const float* w_up      = (const float*)d_in[7];
    const float* w_down    = (const float*)d_in[8];
    const float* g_in_p    = (const float*)d_in[9];
    const float* g_post_at = (const float*)d_in[10];
    const float* g_preff   = (const float*)d_in[11];
    const float* g_postff  = (const float*)d_in[12];
    float* out = (float*)d_out;

    static bool attr_set = false;
    if (!attr_set) {
        cudaFuncSetAttribute(attn_kernel, cudaFuncAttributeMaxDynamicSharedMemorySize,
                             ATTN_SMEM_BYTES);
        attr_set = true;
    }

    // 1) h = rmsnorm(x, g_in)
    rmsnorm_kernel<<<T_, 256>>>(x, g_in_p, nullptr, g_h);
    // 2) QKV projections
    sgemm_kernel<<<dim3(QD_ / 128, T_ / 128), 256>>>(g_h, wq, g_q, T_, QD_, H_);
    sgemm_kernel<<<dim3(KD_ / 128, T_ / 128), 256>>>(g_h, wk, g_k, T_, KD_, H_);
    sgemm_kernel<<<dim3(KD_ / 128, T_ / 128), 256>>>(g_h, wv, g_v, T_, KD_, H_);
    // 3) RoPE
    rope_kernel<NH_ ><<<T_ * NH_  * 128 / 256, 256>>>(g_q);
    rope_kernel<NKV_><<<T_ * NKV_ * 128 / 256, 256>>>(g_k);
    // 4) flash attention (causal, softcap, GQA)
    attn_kernel<<<dim3(S_ / 64, NH_, B_), 256, ATTN_SMEM_BYTES>>>(g_q, g_k, g_v, g_o);
    // 5) O projection
    sgemm_kernel<<<dim3(H_ / 128, T_ / 128), 256>>>(g_o, wo, g_ao, T_, H_, QD_);
    // 6) h2 = x + rmsnorm(attn_out, g_post_attn)
    rmsnorm_kernel<<<T_, 256>>>(g_ao, g_post_at, x, g_h2);
    // 7) f = rmsnorm(h2, g_pre_ff)
    rmsnorm_kernel<<<T_, 256>>>(g_h2, g_preff, nullptr, g_f);
    // 8) gate/up projections
    sgemm_kernel<<<dim3(FF_ / 128, T_ / 128), 256>>>(g_f, w_gate, g_gate, T_, FF_, H_);
    sgemm_kernel<<<dim3(FF_ / 128, T_ / 128), 256>>>(g_f, w_up,   g_up,   T_, FF_, H_);
    // 9) GeGLU (in-place into gate)
    geglu_kernel<<<(size_t)T_ * FF_ / 4 / 256, 256>>>(g_gate, g_up);
    // 10) down projection
    sgemm_kernel<<<dim3(H_ / 128, T_ / 128), 256>>>(g_gate, w_down, g_mlp, T_, H_, FF_);
    // 11) out = h2 + rmsnorm(mlp, g_post_ff)
    rmsnorm_kernel<<<T_, 256>>>(g_mlp, g_postff, g_h2, out);
}